// round 14
// baseline (speedup 1.0000x reference)
#include <cuda_runtime.h>
#include <cuda_bf16.h>
#include <cuda_fp16.h>
#include <cstdint>

// Problem shape (fixed)
#define Bb 4
#define Tt 1024
#define Cc 1024
#define Mm (Bb * Tt)
#define NE (Mm * Cc)
#define WNE (Cc * Cc)

// ---------------------------------------------------------------------------
// Device-global scratch (allocation-free rule)
// ---------------------------------------------------------------------------
__device__ __half g_mk[NE], g_mv[NE], g_mr[NE];
__device__ __half g_at[NE];
__device__ __half g_w[4 * WNE];
__device__ __half g_k16[NE], g_v16[NE], g_r16[NE];

// ---------------------------------------------------------------------------
// PTX helpers (plain sm_80+ features only)
// ---------------------------------------------------------------------------
__device__ __forceinline__ uint32_t smem_u32(const void* p) {
    uint32_t a;
    asm("{ .reg .u64 t; cvta.to.shared.u64 t, %1; cvt.u32.u64 %0, t; }"
        : "=r"(a) : "l"(p));
    return a;
}

#define CP_ASYNC16(dst, src) \
    asm volatile("cp.async.cg.shared.global [%0], [%1], 16;" \
        :: "r"(dst), "l"(src) : "memory")
#define CP_COMMIT() asm volatile("cp.async.commit_group;" ::: "memory")
#define CP_WAIT0()  asm volatile("cp.async.wait_group 0;" ::: "memory")
#define CP_WAIT1()  asm volatile("cp.async.wait_group 1;" ::: "memory")
#define CP_WAIT2()  asm volatile("cp.async.wait_group 2;" ::: "memory")

__device__ __forceinline__ void ldsm_x4(uint32_t* r, uint32_t addr) {
    asm volatile("ldmatrix.sync.aligned.m8n8.x4.shared.b16 {%0,%1,%2,%3}, [%4];"
        : "=r"(r[0]), "=r"(r[1]), "=r"(r[2]), "=r"(r[3]) : "r"(addr));
}

__device__ __forceinline__ void mma16816(float* c, const uint32_t* a,
                                         uint32_t b0, uint32_t b1) {
    asm volatile(
        "mma.sync.aligned.m16n8k16.row.col.f32.f16.f16.f32 "
        "{%0,%1,%2,%3}, {%4,%5,%6,%7}, {%8,%9}, {%0,%1,%2,%3};"
        : "+f"(c[0]), "+f"(c[1]), "+f"(c[2]), "+f"(c[3])
        : "r"(a[0]), "r"(a[1]), "r"(a[2]), "r"(a[3]), "r"(b0), "r"(b1));
}

__device__ __forceinline__ void cvt4h(float4 m, __half* Hb, size_t e0) {
    __half h[4] = { __float2half_rn(m.x), __float2half_rn(m.y),
                    __float2half_rn(m.z), __float2half_rn(m.w) };
    *(uint2*)(Hb + e0) = *(uint2*)h;
}

// ---------------------------------------------------------------------------
// Kernel 1 (merged prep): blocks [0, MIX_BLOCKS)  -> time-shift + mix -> fp16
//                         blocks [MIX_BLOCKS, ..) -> weight fp16 conversion
// ---------------------------------------------------------------------------
#define MIX_BLOCKS  (NE / 4 / 256)
#define WCVT_BLOCKS (4 * WNE / 4 / 256)

__global__ __launch_bounds__(256) void prep_kernel(
    const float* __restrict__ X,
    const float* __restrict__ tmk,
    const float* __restrict__ tmv,
    const float* __restrict__ tmr,
    const float* __restrict__ Wk, const float* __restrict__ Wv,
    const float* __restrict__ Wr, const float* __restrict__ Wo)
{
    if (blockIdx.x < MIX_BLOCKS) {
        int i = blockIdx.x * 256 + threadIdx.x;   // float4 index
        const int PR = Cc / 4;
        int m  = i / PR;
        int c4 = i - m * PR;

        const float4* X4 = (const float4*)X;
        float4 x  = X4[i];
        float4 xp = make_float4(0.f, 0.f, 0.f, 0.f);
        if ((m & (Tt - 1)) != 0) xp = X4[i - PR];

        float4 k4 = ((const float4*)tmk)[c4];
        float4 v4 = ((const float4*)tmv)[c4];
        float4 r4 = ((const float4*)tmr)[c4];

        size_t e0 = (size_t)i * 4;
        float4 o;
        o.x = fmaf(x.x - xp.x, k4.x, xp.x); o.y = fmaf(x.y - xp.y, k4.y, xp.y);
        o.z = fmaf(x.z - xp.z, k4.z, xp.z); o.w = fmaf(x.w - xp.w, k4.w, xp.w);
        cvt4h(o, g_mk, e0);
        o.x = fmaf(x.x - xp.x, v4.x, xp.x); o.y = fmaf(x.y - xp.y, v4.y, xp.y);
        o.z = fmaf(x.z - xp.z, v4.z, xp.z); o.w = fmaf(x.w - xp.w, v4.w, xp.w);
        cvt4h(o, g_mv, e0);
        o.x = fmaf(x.x - xp.x, r4.x, xp.x); o.y = fmaf(x.y - xp.y, r4.y, xp.y);
        o.z = fmaf(x.z - xp.z, r4.z, xp.z); o.w = fmaf(x.w - xp.w, r4.w, xp.w);
        cvt4h(o, g_mr, e0);
    } else {
        int i = (blockIdx.x - MIX_BLOCKS) * 256 + threadIdx.x;
        int sel = i >> 18;                        // WNE/4 = 2^18
        int j   = i & ((WNE / 4) - 1);
        const float* W = (sel == 0) ? Wk : (sel == 1) ? Wv
                       : (sel == 2) ? Wr : Wo;
        float4 v = ((const float4*)W)[j];
        cvt4h(v, g_w + (size_t)sel * WNE, (size_t)j * 4);
    }
}

// ---------------------------------------------------------------------------
// fp16 mma.sync GEMM (single product):  C[M,N] = A[M,K] * W[N,K]^T
// CTA 128x128, BK=32, 512 threads (16 warps, 4m x 4n), warp tile 32x32.
// 4-stage cp.async pipeline (loads 3 chunks ahead), one barrier per chunk.
// OUT16: store fp16 (k/v/r intermediates); else fp32 (final out).
// ---------------------------------------------------------------------------
#define BK 32
#define PITCH 40                       // fp16 elems per smem row (32 + 8 pad)
#define TILE_B (128 * PITCH * 2)       // 10240 B per tile
#define STG    (2 * TILE_B)            // A, W per stage
#define NSTAGE 4
#define SMEM_GEMM (NSTAGE * STG)       // 81920 B
#define NKCH (Cc / BK)                 // 32 chunks

// 512 threads x one 16B unit = a full 128x32 fp16 tile
__device__ __forceinline__ void load_stage_async(
    uint32_t sdst, const __half* __restrict__ A, int m0,
    const __half* __restrict__ W, int n0, int kt, int tid)
{
    int r = tid >> 2;
    int c = tid & 3;
    uint32_t so = (uint32_t)(r * (PITCH * 2) + c * 16);
    size_t go = (size_t)r * Cc + (size_t)kt * BK + c * 8;
    CP_ASYNC16(sdst + so,          (const void*)(A + (size_t)m0 * Cc + go));
    CP_ASYNC16(sdst + TILE_B + so, (const void*)(W + (size_t)n0 * Cc + go));
}

template <bool OUT16>
__device__ __forceinline__ void gemm_body(
    const __half* __restrict__ A, const __half* __restrict__ W,
    void* __restrict__ Cmat)
{
    extern __shared__ char smem[];
    const uint32_t sb = smem_u32(smem);
    int tid = threadIdx.x;
    int wid = tid >> 5;
    int lid = tid & 31;
    int m0 = blockIdx.y * 128;
    int n0 = blockIdx.x * 128;
    int wm = wid & 3;                  // 4 m-groups of 32 rows
    int wn = wid >> 2;                 // 4 n-groups of 32 cols

    float acc[2][4][4];
#pragma unroll
    for (int a = 0; a < 2; a++)
#pragma unroll
        for (int b = 0; b < 4; b++)
#pragma unroll
            for (int c = 0; c < 4; c++) acc[a][b][c] = 0.f;

    // prologue: chunks 0..2 -> stages 0..2
#pragma unroll
    for (int p = 0; p < NSTAGE - 1; p++) {
        load_stage_async(sb + p * STG, A, m0, W, n0, p, tid);
        CP_COMMIT();
    }

    for (int kt = 0; kt < NKCH; kt++) {
        // in-flight groups at this point: chunks [kt, min(kt+2, NKCH-1)]
        if (kt < NKCH - 2)       CP_WAIT2();
        else if (kt == NKCH - 2) CP_WAIT1();
        else                     CP_WAIT0();
        __syncthreads();               // stage kt ready; all warps done kt-1

        if (kt + NSTAGE - 1 < NKCH) {
            load_stage_async(sb + ((kt + NSTAGE - 1) % NSTAGE) * STG,
                             A, m0, W, n0, kt + NSTAGE - 1, tid);
            CP_COMMIT();
        }

        uint32_t sA = sb + (kt % NSTAGE) * STG;
        uint32_t sW = sA + TILE_B;

#pragma unroll
        for (int ks = 0; ks < 2; ks++) {
            int koff = ks * 16 + (lid >> 4) * 8;    // elems
            uint32_t af[2][4];
#pragma unroll
            for (int mi = 0; mi < 2; mi++) {
                int row = wm * 32 + mi * 16 + (lid & 15);
                ldsm_x4(af[mi], sA + (uint32_t)(row * (PITCH * 2) + koff * 2));
            }
            uint32_t wf[2][4];
#pragma unroll
            for (int j2 = 0; j2 < 2; j2++) {
                int nrow = wn * 32 + j2 * 16 + (lid & 15);
                ldsm_x4(wf[j2], sW + (uint32_t)(nrow * (PITCH * 2) + koff * 2));
            }
#pragma unroll
            for (int mi = 0; mi < 2; mi++) {
#pragma unroll
                for (int j = 0; j < 4; j++) {
                    uint32_t b0 = wf[j >> 1][j & 1];
                    uint32_t b1 = wf[j >> 1][(j & 1) + 2];
                    mma16816(acc[mi][j], af[mi], b0, b1);
                }
            }
        }
    }

    // epilogue
#pragma unroll
    for (int mi = 0; mi < 2; mi++) {
        int m = m0 + wm * 32 + mi * 16 + (lid >> 2);
#pragma unroll
        for (int j = 0; j < 4; j++) {
            int n = n0 + wn * 32 + j * 8 + (lid & 3) * 2;
            if (OUT16) {
                __half* C = (__half*)Cmat;
                *(__half2*)(C + (size_t)m * Cc + n) =
                    __floats2half2_rn(acc[mi][j][0], acc[mi][j][1]);
                *(__half2*)(C + (size_t)(m + 8) * Cc + n) =
                    __floats2half2_rn(acc[mi][j][2], acc[mi][j][3]);
            } else {
                float* C = (float*)Cmat;
                *(float2*)(C + (size_t)m * Cc + n) =
                    make_float2(acc[mi][j][0], acc[mi][j][1]);
                *(float2*)(C + (size_t)(m + 8) * Cc + n) =
                    make_float2(acc[mi][j][2], acc[mi][j][3]);
            }
        }
    }
}

__global__ __launch_bounds__(512) void gemm_kvr(void)
{
    if (blockIdx.z == 0)
        gemm_body<true>(g_mk, g_w,           g_k16);
    else if (blockIdx.z == 1)
        gemm_body<true>(g_mv, g_w + WNE,     g_v16);
    else
        gemm_body<true>(g_mr, g_w + 2 * WNE, g_r16);
}

__global__ __launch_bounds__(512) void gemm_out(float* __restrict__ out)
{
    gemm_body<false>(g_at, g_w + 3 * WNE, out);
}

// ---------------------------------------------------------------------------
// Kernel 3: WKV recurrence (chunked 2-pass scan) -> att fp16
// Block = 16 channels x 64 chunks (1024 threads), grid (Cc/16, Bb) = 256 CTAs.
// k/v/r read as fp16 (math in fp32); pass-1 kc/kv cached in registers.
// ---------------------------------------------------------------------------
#define SCHUNKS 64
#define SGRP 16
#define SL (Tt / SCHUNKS)              // 16 timesteps per chunk

__global__ __launch_bounds__(1024) void scan_kernel(
    const float* __restrict__ td, const float* __restrict__ tf)
{
    __shared__ float sA[SCHUNKS][SGRP], sB[SCHUNKS][SGRP];
    __shared__ float sAin[SCHUNKS][SGRP], sBin[SCHUNKS][SGRP];

    int g = threadIdx.x & (SGRP - 1);
    int s = threadIdx.x >> 4;
    int c = blockIdx.x * SGRP + g;
    int b = blockIdx.y;

    float E = __expf(td[c]);
    float f = __expf(-E);
    float p = __expf(tf[c]);

    size_t base = ((size_t)b * Tt + s * SL) * Cc + c;

    // Pass 1: local chunk carries; cache kc/kv in registers
    float kcR[SL], kvR[SL];
    float aL = 0.f, bL = 0.f;
#pragma unroll
    for (int t = 0; t < SL; t++) {
        size_t idx = base + (size_t)t * Cc;
        float kc = __expf(fminf(__half2float(g_k16[idx]), 60.f));
        float kv = kc * __half2float(g_v16[idx]);
        kcR[t] = kc;
        kvR[t] = kv;
        aL = f * aL + kv;
        bL = f * bL + kc;
    }
    sA[s][g] = aL;
    sB[s][g] = bL;
    __syncthreads();

    // Combine chunk carries (threads 0..SGRP-1)
    if (s == 0) {
        float F = __expf(-E * (float)SL);   // f^SL
        float ain = 0.f, bin = 0.f;
#pragma unroll
        for (int ss = 0; ss < SCHUNKS; ss++) {
            sAin[ss][g] = ain;
            sBin[ss][g] = bin;
            ain = F * ain + sA[ss][g];
            bin = F * bin + sB[ss][g];
        }
    }
    __syncthreads();

    // Pass 2: emit att (fp16) using cached kc/kv + correct carry-in
    float a  = sAin[s][g];
    float bb = sBin[s][g];
#pragma unroll
    for (int t = 0; t < SL; t++) {
        size_t idx = base + (size_t)t * Cc;
        float kc = kcR[t];
        float kv = kvR[t];
        float r  = __half2float(g_r16[idx]);
        float sr = 1.f / (1.f + __expf(-r));
        float wkv = p * kv + a;
        float wk  = p * kc + bb + 1e-8f;
        g_at[idx] = __float2half_rn(sr * wkv / wk);
        a  = f * a  + kv;
        bb = f * bb + kc;
    }
}

// ---------------------------------------------------------------------------
// Launch
// ---------------------------------------------------------------------------
extern "C" void kernel_launch(void* const* d_in, const int* in_sizes, int n_in,
                              void* d_out, int out_size)
{
    const float* xq  = (const float*)d_in[0];
    const float* td  = (const float*)d_in[3];
    const float* tf  = (const float*)d_in[4];
    const float* tmk = (const float*)d_in[5];
    const float* tmv = (const float*)d_in[6];
    const float* tmr = (const float*)d_in[7];
    const float* Wk  = (const float*)d_in[8];
    const float* Wv  = (const float*)d_in[9];
    const float* Wr  = (const float*)d_in[10];
    const float* Wo  = (const float*)d_in[11];
    float* out = (float*)d_out;

    static bool attr_done = false;
    if (!attr_done) {
        cudaFuncSetAttribute(gemm_kvr, cudaFuncAttributeMaxDynamicSharedMemorySize, SMEM_GEMM);
        cudaFuncSetAttribute(gemm_out, cudaFuncAttributeMaxDynamicSharedMemorySize, SMEM_GEMM);
        attr_done = true;
    }

    prep_kernel<<<MIX_BLOCKS + WCVT_BLOCKS, 256>>>(
        xq, tmk, tmv, tmr, Wk, Wv, Wr, Wo);

    dim3 gkvr(Cc / 128, Mm / 128, 3);
    gemm_kvr<<<gkvr, 512, SMEM_GEMM>>>();

    dim3 gscan(Cc / SGRP, Bb, 1);
    scan_kernel<<<gscan, 1024>>>(td, tf);

    dim3 go(Cc / 128, Mm / 128, 1);
    gemm_out<<<go, 512, SMEM_GEMM>>>(out);
}

// round 16
// speedup vs baseline: 1.0993x; 1.0993x over previous
#include <cuda_runtime.h>
#include <cuda_bf16.h>
#include <cuda_fp16.h>
#include <cstdint>

// Problem shape (fixed)
#define Bb 4
#define Tt 1024
#define Cc 1024
#define Mm (Bb * Tt)
#define NE (Mm * Cc)
#define WNE (Cc * Cc)

// ---------------------------------------------------------------------------
// Device-global scratch (allocation-free rule)
// ---------------------------------------------------------------------------
__device__ __half g_mk[NE], g_mv[NE], g_mr[NE];
__device__ __half g_at[NE];
__device__ __half g_w[4 * WNE];
__device__ __half g_k16[NE], g_v16[NE], g_r16[NE];

// ---------------------------------------------------------------------------
// PTX helpers (plain sm_80+ features only)
// ---------------------------------------------------------------------------
__device__ __forceinline__ uint32_t smem_u32(const void* p) {
    uint32_t a;
    asm("{ .reg .u64 t; cvta.to.shared.u64 t, %1; cvt.u32.u64 %0, t; }"
        : "=r"(a) : "l"(p));
    return a;
}

#define CP_ASYNC16(dst, src) \
    asm volatile("cp.async.cg.shared.global [%0], [%1], 16;" \
        :: "r"(dst), "l"(src) : "memory")
#define CP_COMMIT() asm volatile("cp.async.commit_group;" ::: "memory")
#define CP_WAIT0()  asm volatile("cp.async.wait_group 0;" ::: "memory")
#define CP_WAIT1()  asm volatile("cp.async.wait_group 1;" ::: "memory")

__device__ __forceinline__ void ldsm_x4(uint32_t* r, uint32_t addr) {
    asm volatile("ldmatrix.sync.aligned.m8n8.x4.shared.b16 {%0,%1,%2,%3}, [%4];"
        : "=r"(r[0]), "=r"(r[1]), "=r"(r[2]), "=r"(r[3]) : "r"(addr));
}

__device__ __forceinline__ void mma16816(float* c, const uint32_t* a,
                                         uint32_t b0, uint32_t b1) {
    asm volatile(
        "mma.sync.aligned.m16n8k16.row.col.f32.f16.f16.f32 "
        "{%0,%1,%2,%3}, {%4,%5,%6,%7}, {%8,%9}, {%0,%1,%2,%3};"
        : "+f"(c[0]), "+f"(c[1]), "+f"(c[2]), "+f"(c[3])
        : "r"(a[0]), "r"(a[1]), "r"(a[2]), "r"(a[3]), "r"(b0), "r"(b1));
}

__device__ __forceinline__ void cvt4h(float4 m, __half* Hb, size_t e0) {
    __half h[4] = { __float2half_rn(m.x), __float2half_rn(m.y),
                    __float2half_rn(m.z), __float2half_rn(m.w) };
    *(uint2*)(Hb + e0) = *(uint2*)h;
}

// ---------------------------------------------------------------------------
// Kernel 1 (merged prep): blocks [0, MIX_BLOCKS)  -> time-shift + mix -> fp16
//                         blocks [MIX_BLOCKS, ..) -> weight fp16 conversion
// ---------------------------------------------------------------------------
#define MIX_BLOCKS  (NE / 4 / 256)
#define WCVT_BLOCKS (4 * WNE / 4 / 256)

__global__ __launch_bounds__(256) void prep_kernel(
    const float* __restrict__ X,
    const float* __restrict__ tmk,
    const float* __restrict__ tmv,
    const float* __restrict__ tmr,
    const float* __restrict__ Wk, const float* __restrict__ Wv,
    const float* __restrict__ Wr, const float* __restrict__ Wo)
{
    if (blockIdx.x < MIX_BLOCKS) {
        int i = blockIdx.x * 256 + threadIdx.x;   // float4 index
        const int PR = Cc / 4;
        int m  = i / PR;
        int c4 = i - m * PR;

        const float4* X4 = (const float4*)X;
        float4 x  = X4[i];
        float4 xp = make_float4(0.f, 0.f, 0.f, 0.f);
        if ((m & (Tt - 1)) != 0) xp = X4[i - PR];

        float4 k4 = ((const float4*)tmk)[c4];
        float4 v4 = ((const float4*)tmv)[c4];
        float4 r4 = ((const float4*)tmr)[c4];

        size_t e0 = (size_t)i * 4;
        float4 o;
        o.x = fmaf(x.x - xp.x, k4.x, xp.x); o.y = fmaf(x.y - xp.y, k4.y, xp.y);
        o.z = fmaf(x.z - xp.z, k4.z, xp.z); o.w = fmaf(x.w - xp.w, k4.w, xp.w);
        cvt4h(o, g_mk, e0);
        o.x = fmaf(x.x - xp.x, v4.x, xp.x); o.y = fmaf(x.y - xp.y, v4.y, xp.y);
        o.z = fmaf(x.z - xp.z, v4.z, xp.z); o.w = fmaf(x.w - xp.w, v4.w, xp.w);
        cvt4h(o, g_mv, e0);
        o.x = fmaf(x.x - xp.x, r4.x, xp.x); o.y = fmaf(x.y - xp.y, r4.y, xp.y);
        o.z = fmaf(x.z - xp.z, r4.z, xp.z); o.w = fmaf(x.w - xp.w, r4.w, xp.w);
        cvt4h(o, g_mr, e0);
    } else {
        int i = (blockIdx.x - MIX_BLOCKS) * 256 + threadIdx.x;
        int sel = i >> 18;                        // WNE/4 = 2^18
        int j   = i & ((WNE / 4) - 1);
        const float* W = (sel == 0) ? Wk : (sel == 1) ? Wv
                       : (sel == 2) ? Wr : Wo;
        float4 v = ((const float4*)W)[j];
        cvt4h(v, g_w + (size_t)sel * WNE, (size_t)j * 4);
    }
}

// ---------------------------------------------------------------------------
// fp16 mma.sync GEMM (single product):  C[M,N] = A[M,K] * W[N,K]^T
// CTA 128x128, BK=32, 512 threads (16 warps, 4m x 4n), warp tile 32x32.
// 3-stage cp.async pipeline (loads 2 chunks ahead), one barrier per chunk.
// OUT16: store fp16 (k/v/r intermediates); else fp32 (final out).
// ---------------------------------------------------------------------------
#define BK 32
#define PITCH 40                       // fp16 elems per smem row (32 + 8 pad)
#define TILE_B (128 * PITCH * 2)       // 10240 B per tile
#define STG    (2 * TILE_B)            // A, W per stage
#define NSTAGE 3
#define SMEM_GEMM (NSTAGE * STG)       // 61440 B
#define NKCH (Cc / BK)                 // 32 chunks

// 512 threads x one 16B unit = a full 128x32 fp16 tile
__device__ __forceinline__ void load_stage_async(
    uint32_t sdst, const __half* __restrict__ A, int m0,
    const __half* __restrict__ W, int n0, int kt, int tid)
{
    int r = tid >> 2;
    int c = tid & 3;
    uint32_t so = (uint32_t)(r * (PITCH * 2) + c * 16);
    size_t go = (size_t)r * Cc + (size_t)kt * BK + c * 8;
    CP_ASYNC16(sdst + so,          (const void*)(A + (size_t)m0 * Cc + go));
    CP_ASYNC16(sdst + TILE_B + so, (const void*)(W + (size_t)n0 * Cc + go));
}

template <bool OUT16>
__device__ __forceinline__ void gemm_body(
    const __half* __restrict__ A, const __half* __restrict__ W,
    void* __restrict__ Cmat)
{
    extern __shared__ char smem[];
    const uint32_t sb = smem_u32(smem);
    int tid = threadIdx.x;
    int wid = tid >> 5;
    int lid = tid & 31;
    int m0 = blockIdx.y * 128;
    int n0 = blockIdx.x * 128;
    int wm = wid & 3;                  // 4 m-groups of 32 rows
    int wn = wid >> 2;                 // 4 n-groups of 32 cols

    float acc[2][4][4];
#pragma unroll
    for (int a = 0; a < 2; a++)
#pragma unroll
        for (int b = 0; b < 4; b++)
#pragma unroll
            for (int c = 0; c < 4; c++) acc[a][b][c] = 0.f;

    // prologue: chunks 0,1 -> stages 0,1
    load_stage_async(sb,       A, m0, W, n0, 0, tid);
    CP_COMMIT();
    load_stage_async(sb + STG, A, m0, W, n0, 1, tid);
    CP_COMMIT();

    for (int kt = 0; kt < NKCH; kt++) {
        if (kt + 2 < NKCH) CP_WAIT1(); else CP_WAIT0();
        __syncthreads();               // stage kt ready; all warps done kt-1

        if (kt + 2 < NKCH) {
            // stage (kt+2)%3 was consumed in chunk kt-1 -> safe to overwrite
            load_stage_async(sb + ((kt + 2) % NSTAGE) * STG,
                             A, m0, W, n0, kt + 2, tid);
            CP_COMMIT();
        }

        uint32_t sA = sb + (kt % NSTAGE) * STG;
        uint32_t sW = sA + TILE_B;

#pragma unroll
        for (int ks = 0; ks < 2; ks++) {
            int koff = ks * 16 + (lid >> 4) * 8;    // elems
            uint32_t af[2][4];
#pragma unroll
            for (int mi = 0; mi < 2; mi++) {
                int row = wm * 32 + mi * 16 + (lid & 15);
                ldsm_x4(af[mi], sA + (uint32_t)(row * (PITCH * 2) + koff * 2));
            }
            uint32_t wf[2][4];
#pragma unroll
            for (int j2 = 0; j2 < 2; j2++) {
                int nrow = wn * 32 + j2 * 16 + (lid & 15);
                ldsm_x4(wf[j2], sW + (uint32_t)(nrow * (PITCH * 2) + koff * 2));
            }
#pragma unroll
            for (int mi = 0; mi < 2; mi++) {
#pragma unroll
                for (int j = 0; j < 4; j++) {
                    uint32_t b0 = wf[j >> 1][j & 1];
                    uint32_t b1 = wf[j >> 1][(j & 1) + 2];
                    mma16816(acc[mi][j], af[mi], b0, b1);
                }
            }
        }
    }

    // epilogue
#pragma unroll
    for (int mi = 0; mi < 2; mi++) {
        int m = m0 + wm * 32 + mi * 16 + (lid >> 2);
#pragma unroll
        for (int j = 0; j < 4; j++) {
            int n = n0 + wn * 32 + j * 8 + (lid & 3) * 2;
            if (OUT16) {
                __half* C = (__half*)Cmat;
                *(__half2*)(C + (size_t)m * Cc + n) =
                    __floats2half2_rn(acc[mi][j][0], acc[mi][j][1]);
                *(__half2*)(C + (size_t)(m + 8) * Cc + n) =
                    __floats2half2_rn(acc[mi][j][2], acc[mi][j][3]);
            } else {
                float* C = (float*)Cmat;
                *(float2*)(C + (size_t)m * Cc + n) =
                    make_float2(acc[mi][j][0], acc[mi][j][1]);
                *(float2*)(C + (size_t)(m + 8) * Cc + n) =
                    make_float2(acc[mi][j][2], acc[mi][j][3]);
            }
        }
    }
}

__global__ __launch_bounds__(512) void gemm_kvr(void)
{
    if (blockIdx.z == 0)
        gemm_body<true>(g_mk, g_w,           g_k16);
    else if (blockIdx.z == 1)
        gemm_body<true>(g_mv, g_w + WNE,     g_v16);
    else
        gemm_body<true>(g_mr, g_w + 2 * WNE, g_r16);
}

__global__ __launch_bounds__(512) void gemm_out(float* __restrict__ out)
{
    gemm_body<false>(g_at, g_w + 3 * WNE, out);
}

// ---------------------------------------------------------------------------
// Kernel 3: WKV recurrence (chunked 2-pass scan) -> att fp16
// Block = 16 channels x 64 chunks (1024 threads), grid (Cc/16, Bb) = 256 CTAs.
// k/v/r read as fp16 (math in fp32); pass-1 kc/kv cached in registers.
// ---------------------------------------------------------------------------
#define SCHUNKS 64
#define SGRP 16
#define SL (Tt / SCHUNKS)              // 16 timesteps per chunk

__global__ __launch_bounds__(1024) void scan_kernel(
    const float* __restrict__ td, const float* __restrict__ tf)
{
    __shared__ float sA[SCHUNKS][SGRP], sB[SCHUNKS][SGRP];
    __shared__ float sAin[SCHUNKS][SGRP], sBin[SCHUNKS][SGRP];

    int g = threadIdx.x & (SGRP - 1);
    int s = threadIdx.x >> 4;
    int c = blockIdx.x * SGRP + g;
    int b = blockIdx.y;

    float E = __expf(td[c]);
    float f = __expf(-E);
    float p = __expf(tf[c]);

    size_t base = ((size_t)b * Tt + s * SL) * Cc + c;

    // Pass 1: local chunk carries; cache kc/kv in registers
    float kcR[SL], kvR[SL];
    float aL = 0.f, bL = 0.f;
#pragma unroll
    for (int t = 0; t < SL; t++) {
        size_t idx = base + (size_t)t * Cc;
        float kc = __expf(fminf(__half2float(g_k16[idx]), 60.f));
        float kv = kc * __half2float(g_v16[idx]);
        kcR[t] = kc;
        kvR[t] = kv;
        aL = f * aL + kv;
        bL = f * bL + kc;
    }
    sA[s][g] = aL;
    sB[s][g] = bL;
    __syncthreads();

    // Combine chunk carries (threads 0..SGRP-1)
    if (s == 0) {
        float F = __expf(-E * (float)SL);   // f^SL
        float ain = 0.f, bin = 0.f;
#pragma unroll
        for (int ss = 0; ss < SCHUNKS; ss++) {
            sAin[ss][g] = ain;
            sBin[ss][g] = bin;
            ain = F * ain + sA[ss][g];
            bin = F * bin + sB[ss][g];
        }
    }
    __syncthreads();

    // Pass 2: emit att (fp16) using cached kc/kv + correct carry-in
    float a  = sAin[s][g];
    float bb = sBin[s][g];
#pragma unroll
    for (int t = 0; t < SL; t++) {
        size_t idx = base + (size_t)t * Cc;
        float kc = kcR[t];
        float kv = kvR[t];
        float r  = __half2float(g_r16[idx]);
        float sr = 1.f / (1.f + __expf(-r));
        float wkv = p * kv + a;
        float wk  = p * kc + bb + 1e-8f;
        g_at[idx] = __float2half_rn(sr * wkv / wk);
        a  = f * a  + kv;
        bb = f * bb + kc;
    }
}

// ---------------------------------------------------------------------------
// Launch
// ---------------------------------------------------------------------------
extern "C" void kernel_launch(void* const* d_in, const int* in_sizes, int n_in,
                              void* d_out, int out_size)
{
    const float* xq  = (const float*)d_in[0];
    const float* td  = (const float*)d_in[3];
    const float* tf  = (const float*)d_in[4];
    const float* tmk = (const float*)d_in[5];
    const float* tmv = (const float*)d_in[6];
    const float* tmr = (const float*)d_in[7];
    const float* Wk  = (const float*)d_in[8];
    const float* Wv  = (const float*)d_in[9];
    const float* Wr  = (const float*)d_in[10];
    const float* Wo  = (const float*)d_in[11];
    float* out = (float*)d_out;

    static bool attr_done = false;
    if (!attr_done) {
        cudaFuncSetAttribute(gemm_kvr, cudaFuncAttributeMaxDynamicSharedMemorySize, SMEM_GEMM);
        cudaFuncSetAttribute(gemm_out, cudaFuncAttributeMaxDynamicSharedMemorySize, SMEM_GEMM);
        attr_done = true;
    }

    prep_kernel<<<MIX_BLOCKS + WCVT_BLOCKS, 256>>>(
        xq, tmk, tmv, tmr, Wk, Wv, Wr, Wo);

    dim3 gkvr(Cc / 128, Mm / 128, 3);
    gemm_kvr<<<gkvr, 512, SMEM_GEMM>>>();

    dim3 gscan(Cc / SGRP, Bb, 1);
    scan_kernel<<<gscan, 1024>>>(td, tf);

    dim3 go(Cc / 128, Mm / 128, 1);
    gemm_out<<<go, 512, SMEM_GEMM>>>(out);
}